// round 15
// baseline (speedup 1.0000x reference)
#include <cuda_runtime.h>
#include <cuda_fp16.h>
#include <math.h>
#include <stdint.h>

// Problem constants
#define B_SZ 4
#define T_SZ 4096
#define V_SZ 1024
#define C_SZ 256
#define L_SZ 64
#define NCH  64
#define BT   (B_SZ * T_SZ)

#define R_SCALE   0.00390625f
#define R_UNSCALE 256.0f

typedef unsigned long long ull;

// ---------------- scratch ---------------------------------------------------
__device__ float g_Wo [V_SZ * C_SZ];
__device__ float g_QKV[3 * BT * C_SZ];       // only V slab (z=2) written fp32
__device__ float g_AS [B_SZ * NCH * C_SZ * C_SZ];   // A^T per chunk (fp32)
__device__ __half g_xh [BT * V_SZ];          // x hi (1-term A)
__device__ __half g_bTh[C_SZ * V_SZ];        // basis^T hi
__device__ __half g_xbh[BT * C_SZ];          // xb hi (1-term A for QKV)
__device__ __half g_xbl[BT * C_SZ];          // unused this round (kept for ABI)
__device__ __half g_ch [3 * C_SZ * C_SZ];    // coeffs hi
__device__ __half g_Woh[V_SZ * C_SZ];        // Wo hi
__device__ __half g_QKh[2 * BT * C_SZ];
__device__ __half g_QKl[2 * BT * C_SZ];
__device__ __half g_Vdth[BT * C_SZ];         // decayed V^T [B][C][T] hi
__device__ __half g_Vdtl[BT * C_SZ];
__device__ __half g_Kth[BT * C_SZ];          // K^T [B][C][T] hi
__device__ __half g_Sth[B_SZ * NCH * C_SZ * C_SZ];  // d^64 * S^T states, hi
__device__ __half g_Rh [BT * C_SZ];          // R hi (1-term A)

__device__ __forceinline__ float get_decay(const float* dl) {
    return 1.0f / (1.0f + expf(-dl[0]));
}

// ---- packed fp32x2 (Wo build only) ----------------------------------------
__device__ __forceinline__ ull pack2(float x) {
    ull r; asm("mov.b64 %0, {%1, %1};" : "=l"(r) : "f"(x)); return r;
}
__device__ __forceinline__ void ffma2(ull& c, ull a, ull b) {
    asm("fma.rn.f32x2 %0, %1, %2, %0;" : "+l"(c) : "l"(a), "l"(b));
}
__device__ __forceinline__ uint32_t cvta_shared(const void* p) {
    uint32_t a;
    asm("{ .reg .u64 t; cvta.to.shared.u64 t, %1; cvt.u32.u64 %0, t; }"
        : "=r"(a) : "l"(p));
    return a;
}

// ---- mma.sync / ldmatrix / cp.async ---------------------------------------
__device__ __forceinline__ void ldsm_x4(uint32_t a, uint32_t* r) {
    asm volatile("ldmatrix.sync.aligned.m8n8.x4.shared.b16 {%0,%1,%2,%3}, [%4];"
                 : "=r"(r[0]), "=r"(r[1]), "=r"(r[2]), "=r"(r[3]) : "r"(a));
}
__device__ __forceinline__ void mma_f16(float* d, const uint32_t* a, const uint32_t* b) {
    asm volatile("mma.sync.aligned.m16n8k16.row.col.f32.f16.f16.f32 "
                 "{%0,%1,%2,%3}, {%4,%5,%6,%7}, {%8,%9}, {%0,%1,%2,%3};"
                 : "+f"(d[0]), "+f"(d[1]), "+f"(d[2]), "+f"(d[3])
                 : "r"(a[0]), "r"(a[1]), "r"(a[2]), "r"(a[3]),
                   "r"(b[0]), "r"(b[1]));
}
__device__ __forceinline__ void cp16(uint32_t dst, const void* src) {
    asm volatile("cp.async.cg.shared.global [%0], [%1], 16;" :: "r"(dst), "l"(src));
}
#define CP_COMMIT() asm volatile("cp.async.commit_group;" ::: "memory")
#define CP_WAIT1()  asm volatile("cp.async.wait_group 1;" ::: "memory")
#define CP_WAIT0()  asm volatile("cp.async.wait_group 0;" ::: "memory")

__device__ __forceinline__ void split_store2(__half* H, __half* L, float v0, float v1) {
    __half h0 = __float2half_rn(v0), h1 = __float2half_rn(v1);
    *(__half2*)H = __half2(h0, h1);
    if (L) *(__half2*)L = __half2(__float2half_rn(v0 - __half2float(h0)),
                                  __float2half_rn(v1 - __half2float(h1)));
}

// smem geometry for mma_gemm
#define BK 32
#define ROWB 80
#define ARR_B (128 * ROWB)

// ===========================================================================
// fp16 tensor-core GEMM, ATERMS A-side passes (1 or 2): C = A @ Bh^T.
// Epilogue: z < nhz -> fp16 hi (+lo if Lout); else fp32.
// NOTE: launched with padded dynamic smem where 1-CTA/SM occupancy is wanted.
// ===========================================================================
template <int ATERMS>
__global__ void __launch_bounds__(256) mma_gemm(
    const __half* __restrict__ Ahb, const __half* __restrict__ Alb,
    const __half* __restrict__ Bhb,
    float* __restrict__ Cbase, __half* __restrict__ Hout, __half* __restrict__ Lout,
    int nhz, size_t sH, int K, size_t sB, size_t sC, int ldC,
    const float* __restrict__ scale_ptr, float alpha_mul)
{
    extern __shared__ __align__(16) char dynsm[];
    const uint32_t sdyn = cvta_shared(dynsm);
    const uint32_t STAGE_B = (ATERMS + 1) * ARR_B;
    const uint32_t BOFF = ATERMS * ARR_B;

    const int tid = threadIdx.x, lane = tid & 31, wid = tid >> 5;
    const int m0 = blockIdx.y * 128, n0 = blockIdx.x * 128;
    const int z = blockIdx.z;
    const __half* gAh = Ahb + (size_t)m0 * K;
    const __half* gAl = Alb + (size_t)m0 * K;
    const __half* gBh = Bhb + (size_t)z * sB + (size_t)n0 * K;

    const int warp_m = wid >> 1, warp_n = wid & 1;
    const int r8 = lane & 7, midx = lane >> 3;
    const int NC = K / BK;
    const int lr0 = tid >> 2, c4 = tid & 3;

    float acc[2][8][4];
#pragma unroll
    for (int mt = 0; mt < 2; mt++)
#pragma unroll
        for (int nt = 0; nt < 8; nt++)
#pragma unroll
            for (int r = 0; r < 4; r++) acc[mt][nt][r] = 0.0f;

    auto issue = [&](int s, int kc) {
        const int k0 = kc * BK;
        const uint32_t st = sdyn + s * STAGE_B;
#pragma unroll
        for (int h = 0; h < 2; h++) {
            const int r = lr0 + h * 64;
            const uint32_t d = st + r * ROWB + c4 * 16;
            const size_t g = (size_t)r * K + k0 + c4 * 8;
            cp16(d, gAh + g);
            if (ATERMS == 2) cp16(d + ARR_B, gAl + g);
            cp16(d + BOFF, gBh + g);
        }
        CP_COMMIT();
    };

    issue(0, 0);
    issue(1, 1);

    for (int i = 0; i < NC; i++) {
        if (i < NC - 1) CP_WAIT1(); else CP_WAIT0();
        __syncthreads();
        if (i + 2 < NC) issue((i + 2) % 3, i + 2);

        const uint32_t stg = sdyn + (i % 3) * STAGE_B;
#pragma unroll
        for (int kh = 0; kh < 2; kh++) {
            uint32_t ah[2][4], al[2][4], bh4[4][4];
#pragma unroll
            for (int mt = 0; mt < 2; mt++) {
                const uint32_t ad = stg +
                    (warp_m * 32 + mt * 16 + (midx & 1) * 8 + r8) * ROWB +
                    (midx >> 1) * 16 + kh * 32;
                ldsm_x4(ad, ah[mt]);
                if (ATERMS == 2) ldsm_x4(ad + ARR_B, al[mt]);
            }
#pragma unroll
            for (int ng = 0; ng < 4; ng++) {
                const uint32_t bd = stg + BOFF +
                    (warp_n * 64 + ng * 16 + (midx >> 1) * 8 + r8) * ROWB +
                    (midx & 1) * 16 + kh * 32;
                ldsm_x4(bd, bh4[ng]);
            }
#pragma unroll
            for (int mt = 0; mt < 2; mt++)
#pragma unroll
                for (int nt = 0; nt < 8; nt++) {
                    const uint32_t* bp = &bh4[nt >> 1][(nt & 1) * 2];
                    mma_f16(acc[mt][nt], ah[mt], bp);
                    if (ATERMS == 2) mma_f16(acc[mt][nt], al[mt], bp);
                }
        }
    }

    const float alpha = (scale_ptr ? scale_ptr[0] : 1.0f) * alpha_mul;
    const int crow = lane >> 2, ccol = (lane & 3) * 2;
    if (z < nhz) {
        __half* H = Hout + (size_t)z * sH;
        __half* L = Lout ? Lout + (size_t)z * sH : nullptr;
#pragma unroll
        for (int mt = 0; mt < 2; mt++)
#pragma unroll
            for (int nt = 0; nt < 8; nt++) {
                const int row = m0 + warp_m * 32 + mt * 16 + crow;
                const int col = n0 + warp_n * 64 + nt * 8 + ccol;
                const size_t o = (size_t)row * ldC + col;
                split_store2(H + o, L ? L + o : nullptr,
                             acc[mt][nt][0] * alpha, acc[mt][nt][1] * alpha);
                const size_t o2 = o + 8 * (size_t)ldC;
                split_store2(H + o2, L ? L + o2 : nullptr,
                             acc[mt][nt][2] * alpha, acc[mt][nt][3] * alpha);
            }
    } else {
        float* C = Cbase + (size_t)z * sC;
#pragma unroll
        for (int mt = 0; mt < 2; mt++)
#pragma unroll
            for (int nt = 0; nt < 8; nt++) {
                const int row = m0 + warp_m * 32 + mt * 16 + crow;
                const int col = n0 + warp_n * 64 + nt * 8 + ccol;
                float* p = C + (size_t)row * ldC + col;
                *(float2*)p = make_float2(acc[mt][nt][0] * alpha, acc[mt][nt][1] * alpha);
                *(float2*)(p + 8 * (size_t)ldC) =
                    make_float2(acc[mt][nt][2] * alpha, acc[mt][nt][3] * alpha);
            }
    }
}

// ===========================================================================
// chunk_mma: A^T[c2][c1] = sum_r d^r V[r,c2] K[r,c1] per chunk (fp32 out)
// ===========================================================================
#define CK_STR 144
#define CK_AH 0
#define CK_AL 18432
#define CK_B  36864
#define CK_SMEM 55296

__global__ void __launch_bounds__(256) chunk_mma()
{
    extern __shared__ __align__(16) char csm[];
    const uint32_t s0 = cvta_shared(csm);
    const int z = blockIdx.z, b = z >> 6, c = z & 63;
    const int m0 = blockIdx.y * 128, n0 = blockIdx.x * 128;
    const int tid = threadIdx.x, lane = tid & 31, wid = tid >> 5;
    const int r8 = lane & 7, midx = lane >> 3;

    const size_t tb = (size_t)b * C_SZ * T_SZ + (size_t)c * 64;
    const __half* gAh = g_Vdth + tb + (size_t)m0 * T_SZ;
    const __half* gAl = g_Vdtl + tb + (size_t)m0 * T_SZ;
    const __half* gB  = g_Kth  + tb + (size_t)n0 * T_SZ;

    {
        const int row = tid >> 1, c2_ = tid & 1;
#pragma unroll
        for (int it = 0; it < 4; it++) {
            const int cc = c2_ + it * 2;
            const size_t g = (size_t)row * T_SZ + cc * 8;
            cp16(s0 + CK_AH + row * CK_STR + cc * 16, gAh + g);
            cp16(s0 + CK_AL + row * CK_STR + cc * 16, gAl + g);
            cp16(s0 + CK_B  + row * CK_STR + cc * 16, gB + g);
        }
        CP_COMMIT();
    }
    CP_WAIT0();
    __syncthreads();

    const int wm = wid >> 1, wn = wid & 1;
    float acc[2][8][4];
#pragma unroll
    for (int mt = 0; mt < 2; mt++)
#pragma unroll
        for (int nt = 0; nt < 8; nt++)
#pragma unroll
            for (int e = 0; e < 4; e++) acc[mt][nt][e] = 0.0f;

#pragma unroll
    for (int ks = 0; ks < 4; ks++) {
        uint32_t ah[2][4], al[2][4], bt[4][4];
#pragma unroll
        for (int mt = 0; mt < 2; mt++) {
            const uint32_t ad = s0 + CK_AH +
                (wm * 32 + mt * 16 + (midx & 1) * 8 + r8) * CK_STR +
                (ks * 16 + (midx >> 1) * 8) * 2;
            ldsm_x4(ad, ah[mt]);
            ldsm_x4(ad + (CK_AL - CK_AH), al[mt]);
        }
#pragma unroll
        for (int ng = 0; ng < 4; ng++) {
            const uint32_t bd = s0 + CK_B +
                (wn * 64 + ng * 16 + (midx >> 1) * 8 + r8) * CK_STR +
                (ks * 16 + (midx & 1) * 8) * 2;
            ldsm_x4(bd, bt[ng]);
        }
#pragma unroll
        for (int mt = 0; mt < 2; mt++)
#pragma unroll
            for (int nt = 0; nt < 8; nt++) {
                const uint32_t* bp = &bt[nt >> 1][(nt & 1) * 2];
                mma_f16(acc[mt][nt], ah[mt], bp);
                mma_f16(acc[mt][nt], al[mt], bp);
            }
    }

    float* O = g_AS + (size_t)z * C_SZ * C_SZ;
    const int crow = lane >> 2, ccol = (lane & 3) * 2;
#pragma unroll
    for (int mt = 0; mt < 2; mt++)
#pragma unroll
        for (int nt = 0; nt < 8; nt++) {
            const int row = m0 + wm * 32 + mt * 16 + crow;
            const int col = n0 + wn * 64 + nt * 8 + ccol;
            float* p = O + (size_t)row * C_SZ + col;
            *(float2*)p = make_float2(acc[mt][nt][0], acc[mt][nt][1]);
            *(float2*)(p + 8 * C_SZ) = make_float2(acc[mt][nt][2], acc[mt][nt][3]);
        }
}

// ===========================================================================
// attn: P = mask(Q K^T); acc = Q@Std (2-term) + P@Vdt (3-term);
// epilogue scales rows by d^(-i-1)*R_SCALE, writes Rh only.
// ===========================================================================
#define AQ_STR 528
#define AP_STR 144
#define AB_STR 80
#define A_SQH  0
#define A_SQL  33792
#define A_SPH  67584
#define A_SPL  76800
#define A_BUF  86016
#define A_STG  40960
#define A_SMEM 208896

__global__ void __launch_bounds__(256) attn_mma(const float* __restrict__ dlp)
{
    extern __shared__ __align__(16) char asmm[];
    const uint32_t s0 = cvta_shared(asmm);
    const int c = blockIdx.x, b = blockIdx.y;
    const int tid = threadIdx.x, lane = tid & 31, wid = tid >> 5;
    const float lg2d = log2f(get_decay(dlp));

    const size_t nat = ((size_t)b * T_SZ + (size_t)c * L_SZ) * C_SZ;
    const __half* gQh = g_QKh + nat;
    const __half* gQl = g_QKl + nat;
    const __half* gKh = g_QKh + (size_t)BT * C_SZ + nat;
    const __half* gKl = g_QKl + (size_t)BT * C_SZ + nat;
    const size_t vt = (size_t)b * C_SZ * T_SZ + (size_t)c * L_SZ;
    const size_t st = ((size_t)(b * NCH + c)) * C_SZ * C_SZ;

    const int r8 = lane & 7, midx = lane >> 3;

    {
        const int row = tid >> 2, q4 = tid & 3;
#pragma unroll
        for (int it = 0; it < 8; it++) {
            const int c16 = q4 + it * 4;
            cp16(s0 + A_SQH + row * AQ_STR + c16 * 16, gQh + row * C_SZ + c16 * 8);
            cp16(s0 + A_SQL + row * AQ_STR + c16 * 16, gQl + row * C_SZ + c16 * 8);
        }
        CP_COMMIT();
    }

    auto issue = [&](int q) {
        const uint32_t bh = s0 + A_BUF + (q % 3) * A_STG;
        const uint32_t bl = bh + 20480;
        if (q < 8) {
            const int row = tid >> 2, c16 = tid & 3;
            cp16(bh + row * AB_STR + c16 * 16, gKh + row * C_SZ + q * 32 + c16 * 8);
            cp16(bl + row * AB_STR + c16 * 16, gKl + row * C_SZ + q * 32 + c16 * 8);
        } else if (q < 16) {
            const int ct = q - 8;
            const size_t src = st + (size_t)tid * C_SZ + ct * 32;
#pragma unroll
            for (int it = 0; it < 4; it++)
                cp16(bh + tid * AB_STR + it * 16, g_Sth + src + it * 8);
        } else {
            const int ct = q - 16;
            const size_t src = vt + (size_t)tid * T_SZ + ct * 32;
#pragma unroll
            for (int it = 0; it < 4; it++) {
                cp16(bh + tid * AB_STR + it * 16, g_Vdth + src + it * 8);
                cp16(bl + tid * AB_STR + it * 16, g_Vdtl + src + it * 8);
            }
        }
        CP_COMMIT();
    };

    const int pwm = wid & 3, pwn = wid >> 2;
    const int wm = wid & 1, wn = wid >> 1;

    float accp[4][4];
#pragma unroll
    for (int a = 0; a < 4; a++)
#pragma unroll
        for (int e = 0; e < 4; e++) accp[a][e] = 0.0f;
    float acc[2][8][4];
#pragma unroll
    for (int mt = 0; mt < 2; mt++)
#pragma unroll
        for (int nt = 0; nt < 8; nt++)
#pragma unroll
            for (int e = 0; e < 4; e++) acc[mt][nt][e] = 0.0f;

    issue(0);
    issue(1);

    for (int q = 0; q < 18; q++) {
        if (q < 17) CP_WAIT1(); else CP_WAIT0();
        __syncthreads();
        if (q + 2 < 18) issue(q + 2);

        const uint32_t bh = s0 + A_BUF + (q % 3) * A_STG;

        if (q < 8) {
#pragma unroll
            for (int ks = 0; ks < 2; ks++) {
                uint32_t ah[4], al[4];
                const uint32_t ad = s0 + A_SQH +
                    (pwm * 16 + (midx & 1) * 8 + r8) * AQ_STR +
                    (q * 32 + ks * 16 + (midx >> 1) * 8) * 2;
                ldsm_x4(ad, ah);
                ldsm_x4(ad + (A_SQL - A_SQH), al);
#pragma unroll
                for (int ng = 0; ng < 2; ng++) {
                    uint32_t bhf[4], blf[4];
                    const uint32_t bd = bh +
                        (pwn * 32 + ng * 16 + (midx >> 1) * 8 + r8) * AB_STR +
                        (ks * 16 + (midx & 1) * 8) * 2;
                    ldsm_x4(bd, bhf);
                    ldsm_x4(bd + 20480, blf);
#pragma unroll
                    for (int sub = 0; sub < 2; sub++) {
                        float* A = accp[ng * 2 + sub];
                        mma_f16(A, ah, &bhf[sub * 2]);
                        mma_f16(A, al, &bhf[sub * 2]);
                        mma_f16(A, ah, &blf[sub * 2]);
                    }
                }
            }
            if (q == 7) {
                const int prow = pwm * 16 + (lane >> 2);
#pragma unroll
                for (int nt = 0; nt < 4; nt++)
#pragma unroll
                    for (int e = 0; e < 4; e++) {
                        const int i = prow + (e >> 1) * 8;
                        const int j = pwn * 32 + nt * 8 + (lane & 3) * 2 + (e & 1);
                        float v = (j > i) ? accp[nt][e] : 0.0f;
                        __half h = __float2half_rn(v);
                        *(__half*)(asmm + A_SPH + i * AP_STR + j * 2) = h;
                        *(__half*)(asmm + A_SPL + i * AP_STR + j * 2) =
                            __float2half_rn(v - __half2float(h));
                    }
            }
        } else if (q < 16) {
            const int ct = q - 8;
#pragma unroll
            for (int ks = 0; ks < 2; ks++) {
                uint32_t ah[2][4], al[2][4], bh4[4][4];
#pragma unroll
                for (int mt = 0; mt < 2; mt++) {
                    const uint32_t ad = s0 + A_SQH +
                        (wm * 32 + mt * 16 + (midx & 1) * 8 + r8) * AQ_STR +
                        (ct * 32 + ks * 16 + (midx >> 1) * 8) * 2;
                    ldsm_x4(ad, ah[mt]);
                    ldsm_x4(ad + (A_SQL - A_SQH), al[mt]);
                }
#pragma unroll
                for (int ng = 0; ng < 4; ng++) {
                    const uint32_t bd = bh +
                        (wn * 64 + ng * 16 + (midx >> 1) * 8 + r8) * AB_STR +
                        (ks * 16 + (midx & 1) * 8) * 2;
                    ldsm_x4(bd, bh4[ng]);
                }
#pragma unroll
                for (int mt = 0; mt < 2; mt++)
#pragma unroll
                    for (int nt = 0; nt < 8; nt++) {
                        const uint32_t* bp = &bh4[nt >> 1][(nt & 1) * 2];
                        mma_f16(acc[mt][nt], ah[mt], bp);
                        mma_f16(acc[mt][nt], al[mt], bp);
                    }
            }
        } else {
#pragma unroll
            for (int ks = 0; ks < 2; ks++) {
                uint32_t ah[2][4], al[2][4], bh4[4][4], bl4[4][4];
                const int ct = q - 16;
#pragma unroll
                for (int mt = 0; mt < 2; mt++) {
                    const uint32_t ad = s0 + A_SPH +
                        (wm * 32 + mt * 16 + (midx & 1) * 8 + r8) * AP_STR +
                        (ct * 32 + ks * 16 + (midx >> 1) * 8) * 2;
                    ldsm_x4(ad, ah[mt]);
                    ldsm_x4(ad + (A_SPL - A_SPH), al[mt]);
                }
#pragma unroll
                for (int ng = 0; ng < 4; ng++) {
                    const uint32_t bd = bh +
                        (wn * 64 + ng * 16 + (midx >> 1) * 8 + r8) * AB_STR +
                        (ks * 16 + (midx & 1) * 8) * 2;
                    ldsm_x4(bd, bh4[ng]);
                    ldsm_x4(bd + 20480, bl4[ng]);
                }
#pragma unroll
                for (int mt = 0; mt < 2; mt++)
#pragma unroll
                    for (int nt = 0; nt < 8; nt++) {
                        const uint32_t* bp  = &bh4[nt >> 1][(nt & 1) * 2];
                        const uint32_t* blp = &bl4[nt >> 1][(nt & 1) * 2];
                        mma_f16(acc[mt][nt], ah[mt], bp);
                        mma_f16(acc[mt][nt], al[mt], bp);
                        mma_f16(acc[mt][nt], ah[mt], blp);
                    }
            }
        }
    }

    __half* Rh = g_Rh + nat;
#pragma unroll
    for (int mt = 0; mt < 2; mt++) {
        const int i0 = wm * 32 + mt * 16 + (lane >> 2);
        const float s1 = exp2f(-(float)(i0 + 1) * lg2d) * R_SCALE;
        const float s2 = exp2f(-(float)(i0 + 9) * lg2d) * R_SCALE;
#pragma unroll
        for (int nt = 0; nt < 8; nt++) {
            const int col = wn * 64 + nt * 8 + (lane & 3) * 2;
            const size_t o = (size_t)i0 * C_SZ + col;
            *(__half2*)(Rh + o) = __half2(__float2half_rn(acc[mt][nt][0] * s1),
                                          __float2half_rn(acc[mt][nt][1] * s1));
            const size_t o2 = o + 8 * (size_t)C_SZ;
            *(__half2*)(Rh + o2) = __half2(__float2half_rn(acc[mt][nt][2] * s2),
                                           __float2half_rn(acc[mt][nt][3] * s2));
        }
    }
}

// ===========================================================================
// fp32 -> fp16 hi only
// ===========================================================================
__global__ void tohalf_kernel(const float* __restrict__ s,
                              __half* __restrict__ h, int n4)
{
    int i = blockIdx.x * blockDim.x + threadIdx.x;
    if (i >= n4) return;
    float4 v = ((const float4*)s)[i];
    ((__half2*)h)[2 * i]     = __half2(__float2half_rn(v.x), __float2half_rn(v.y));
    ((__half2*)h)[2 * i + 1] = __half2(__float2half_rn(v.z), __float2half_rn(v.w));
}

// ===========================================================================
// basis [1024,256] -> basis^T fp16 hi
// ===========================================================================
__global__ void transpose_half(const float* __restrict__ in,
                               __half* __restrict__ oh)
{
    __shared__ float t[32][33];
    const int v0 = blockIdx.x * 32, c0 = blockIdx.y * 32;
    const int tx = threadIdx.x, ty = threadIdx.y;
#pragma unroll
    for (int j = 0; j < 32; j += 8)
        t[ty + j][tx] = in[(size_t)(v0 + ty + j) * C_SZ + c0 + tx];
    __syncthreads();
#pragma unroll
    for (int j = 0; j < 32; j += 8)
        oh[(size_t)(c0 + ty + j) * V_SZ + v0 + tx] = __float2half_rn(t[tx][ty + j]);
}

// ===========================================================================
// V [B*T, C] fp32 -> decayed V^T [B][C][T] fp16 hi/lo (decay d^(t mod 64))
// ===========================================================================
__global__ void transpose_split_vd(const float* __restrict__ in,
                                   __half* __restrict__ oh, __half* __restrict__ ol,
                                   const float* __restrict__ dlp)
{
    __shared__ float t[32][33];
    const int b = blockIdx.z;
    const int t0 = blockIdx.x * 32, c0 = blockIdx.y * 32;
    const int tx = threadIdx.x, ty = threadIdx.y;
    const float lg2d = log2f(get_decay(dlp));
    const float dr = exp2f((float)((t0 + tx) & 63) * lg2d);
#pragma unroll
    for (int j = 0; j < 32; j += 8)
        t[ty + j][tx] = in[((size_t)b * T_SZ + t0 + ty + j) * C_SZ + c0 + tx];
    __syncthreads();
#pragma unroll
    for (int j = 0; j < 32; j += 8) {
        float val = t[tx][ty + j] * dr;
        __half h = __float2half_rn(val);
        const size_t o = (size_t)b * C_SZ * T_SZ + (size_t)(c0 + ty + j) * T_SZ + t0 + tx;
        oh[o] = h;
        ol[o] = __float2half_rn(val - __half2float(h));
    }
}

// ===========================================================================
// K hi [B*T, C] fp16 -> K^T [B][C][T] fp16 hi
// ===========================================================================
__global__ void transpose_h(const __half* __restrict__ in, __half* __restrict__ out)
{
    __shared__ __half t[32][33];
    const int b = blockIdx.z;
    const int t0 = blockIdx.x * 32, c0 = blockIdx.y * 32;
    const int tx = threadIdx.x, ty = threadIdx.y;
#pragma unroll
    for (int j = 0; j < 32; j += 8)
        t[ty + j][tx] = in[((size_t)b * T_SZ + t0 + ty + j) * C_SZ + c0 + tx];
    __syncthreads();
#pragma unroll
    for (int j = 0; j < 32; j += 8)
        out[(size_t)b * C_SZ * T_SZ + (size_t)(c0 + ty + j) * T_SZ + t0 + tx] =
            t[tx][ty + j];
}

// ===========================================================================
// SGEMM nt (f32x2) — Wo build only
// ===========================================================================
__global__ void __launch_bounds__(256) sgemm_nt(
    const float* __restrict__ A, const float* __restrict__ B,
    float* __restrict__ C, int M, int N, int K)
{
    __shared__ __align__(16) float As[8][128];
    __shared__ __align__(16) float Bs[8][128];
    const int tid = threadIdx.x;
    const int m0 = blockIdx.y * 128, n0 = blockIdx.x * 128;
    const int tr = tid >> 4, tc = tid & 15;
    const int ar = tid >> 1, ac = (tid & 1) * 4;
    ull acc[8][4] = {};
    const float* Aptr = A + (size_t)(m0 + ar) * K + ac;
    const float* Bptr = B + (size_t)(n0 + ar) * K + ac;
    for (int k0 = 0; k0 < K; k0 += 8) {
        float4 av = *(const float4*)(Aptr + k0);
        As[ac + 0][ar] = av.x; As[ac + 1][ar] = av.y;
        As[ac + 2][ar] = av.z; As[ac + 3][ar] = av.w;
        float4 bv = *(const float4*)(Bptr + k0);
        Bs[ac + 0][ar] = bv.x; Bs[ac + 1][ar] = bv.y;
        Bs[ac + 2][ar] = bv.z; Bs[ac + 3][ar] = bv.w;
        __syncthreads();
#pragma unroll
        for (int kk = 0; kk < 8; kk++) {
            const ull* bp = (const ull*)&Bs[kk][tc * 8];
            ull b0 = bp[0], b1 = bp[1], b2 = bp[2], b3 = bp[3];
            const float* ap = &As[kk][tr * 8];
#pragma unroll
            for (int i = 0; i < 8; i++) {
                ull a2 = pack2(ap[i]);
                ffma2(acc[i][0], a2, b0); ffma2(acc[i][1], a2, b1);
                ffma2(acc[i][2], a2, b2); ffma2(acc[i][3], a2, b3);
            }
        }
        __syncthreads();
    }
#pragma unroll
    for (int i = 0; i < 8; i++) {
        float* Cp = C + (size_t)(m0 + tr * 8 + i) * N + n0 + tc * 8;
        float2 p0 = *(float2*)&acc[i][0], p1 = *(float2*)&acc[i][1];
        float2 p2 = *(float2*)&acc[i][2], p3 = *(float2*)&acc[i][3];
        *(float4*)(Cp)     = make_float4(p0.x, p0.y, p1.x, p1.y);
        *(float4*)(Cp + 4) = make_float4(p2.x, p2.y, p3.x, p3.y);
    }
}

// ===========================================================================
// scan: run=0; for c desc: store d^64*run (fp16 hi); run = d^64*run + A[c]
// ===========================================================================
__global__ void scan_kernel(const float* __restrict__ dlp)
{
    const int e = blockIdx.x * blockDim.x + threadIdx.x;
    const int b = blockIdx.y;
    const float decay = get_decay(dlp);
    const float dL = exp2f((float)L_SZ * log2f(decay));
    float run = 0.0f;
    const size_t base = (size_t)b * NCH * (C_SZ * C_SZ) + e;
    for (int c = NCH - 1; c >= 0; c--) {
        const size_t pos = base + (size_t)c * (C_SZ * C_SZ);
        const float sc_ = dL * run;
        g_Sth[pos] = __float2half_rn(sc_);
        run = sc_ + g_AS[pos];
    }
}

// ===========================================================================
extern "C" void kernel_launch(void* const* d_in, const int* in_sizes, int n_in,
                              void* d_out, int out_size)
{
    const float* x     = (const float*)d_in[0];
    const float* basis = (const float*)d_in[1];
    const float* qc    = (const float*)d_in[2];
    const float* kc    = (const float*)d_in[3];
    const float* vc    = (const float*)d_in[4];
    const float* oc    = (const float*)d_in[5];
    const float* dl    = (const float*)d_in[6];
    const float* os    = (const float*)d_in[7];
    float* out = (float*)d_out;

    float *pWo, *pQKV, *pAS;
    __half *pxh, *pbTh, *pxbh, *pch, *pWoh;
    __half *pQKh, *pQKl, *pVdth, *pVdtl, *pKth, *pRh;
    cudaGetSymbolAddress((void**)&pWo,   g_Wo);
    cudaGetSymbolAddress((void**)&pQKV,  g_QKV);
    cudaGetSymbolAddress((void**)&pAS,   g_AS);
    cudaGetSymbolAddress((void**)&pxh,   g_xh);
    cudaGetSymbolAddress((void**)&pbTh,  g_bTh);
    cudaGetSymbolAddress((void**)&pxbh,  g_xbh);
    cudaGetSymbolAddress((void**)&pch,   g_ch);
    cudaGetSymbolAddress((void**)&pWoh,  g_Woh);
    cudaGetSymbolAddress((void**)&pQKh,  g_QKh);
    cudaGetSymbolAddress((void**)&pQKl,  g_QKl);
    cudaGetSymbolAddress((void**)&pVdth, g_Vdth);
    cudaGetSymbolAddress((void**)&pVdtl, g_Vdtl);
    cudaGetSymbolAddress((void**)&pKth,  g_Kth);
    cudaGetSymbolAddress((void**)&pRh,   g_Rh);

    const int SMEM_A1  = 3 * 2 * ARR_B;   // 61440  (xb, out — unchanged controls)
    const int SMEM_PAD = 3 * 3 * ARR_B;   // 92160  (QKV 1-term, padded -> 1 CTA/SM)
    cudaFuncSetAttribute(mma_gemm<1>, cudaFuncAttributeMaxDynamicSharedMemorySize, SMEM_PAD);
    cudaFuncSetAttribute(chunk_mma, cudaFuncAttributeMaxDynamicSharedMemorySize, CK_SMEM);
    cudaFuncSetAttribute(attn_mma, cudaFuncAttributeMaxDynamicSharedMemorySize, A_SMEM);

    // 1. prep: basis^T hi, x hi, coeffs hi, Wo build + hi
    transpose_half<<<dim3(32, 8), dim3(32, 8)>>>(basis, pbTh);
    tohalf_kernel<<<(BT * V_SZ / 4 + 255) / 256, 256>>>(x, pxh, BT * V_SZ / 4);
    tohalf_kernel<<<(C_SZ * C_SZ / 4 + 255) / 256, 256>>>(qc, pch, C_SZ * C_SZ / 4);
    tohalf_kernel<<<(C_SZ * C_SZ / 4 + 255) / 256, 256>>>(kc, pch + C_SZ * C_SZ, C_SZ * C_SZ / 4);
    tohalf_kernel<<<(C_SZ * C_SZ / 4 + 255) / 256, 256>>>(vc, pch + 2 * C_SZ * C_SZ, C_SZ * C_SZ / 4);
    sgemm_nt<<<dim3(2, 8), 256>>>(basis, oc, pWo, 1024, 256, 256);
    tohalf_kernel<<<(V_SZ * C_SZ / 4 + 255) / 256, 256>>>(pWo, pWoh, V_SZ * C_SZ / 4);

    // 2. xb = x @ basis (1-term A, 61KB as in best config) -> fp16 hi only
    mma_gemm<1><<<dim3(2, 128, 1), 256, SMEM_A1>>>(
        pxh, pxh, pbTh, pAS /*dummy*/, pxbh, nullptr, 1, 0,
        V_SZ, 0, 0, C_SZ, nullptr, 1.0f);

    // 3. QKV = xb @ coeffs^T (1-term A, smem PADDED to 92KB -> occ 1):
    //    z=0,1 -> Q/K fp16 hi/lo; z=2 -> V fp32
    mma_gemm<1><<<dim3(2, 128, 3), 256, SMEM_PAD>>>(
        pxbh, pxbh, pch, pQKV, pQKh, pQKl, 2, (size_t)BT * C_SZ,
        C_SZ, (size_t)C_SZ * C_SZ, (size_t)BT * C_SZ, C_SZ, nullptr, 1.0f);

    // 4. transposes: decayed V^T hi/lo, K^T hi
    transpose_split_vd<<<dim3(128, 8, B_SZ), dim3(32, 8)>>>(
        pQKV + 2 * (size_t)BT * C_SZ, pVdth, pVdtl, dl);
    transpose_h<<<dim3(128, 8, B_SZ), dim3(32, 8)>>>(pQKh + (size_t)BT * C_SZ, pKth);

    // 5. chunk A^T, scan -> fp16 states, attn -> Rh
    chunk_mma<<<dim3(2, 2, B_SZ * NCH), 256, CK_SMEM>>>();
    scan_kernel<<<dim3(256, B_SZ), 256>>>(dl);
    attn_mma<<<dim3(NCH, B_SZ), 256, A_SMEM>>>(dl);

    // 6. output projection: out = R @ Wo^T * out_scale (1-term A, 61KB)
    mma_gemm<1><<<dim3(8, 128, 1), 256, SMEM_A1>>>(
        pRh, pRh, pWoh, out, nullptr, nullptr, 0, 0,
        C_SZ, 0, 0, V_SZ, os, R_UNSCALE);
}

// round 17
// speedup vs baseline: 1.5154x; 1.5154x over previous
#include <cuda_runtime.h>
#include <cuda_fp16.h>
#include <math.h>
#include <stdint.h>

// Problem constants
#define B_SZ 4
#define T_SZ 4096
#define V_SZ 1024
#define C_SZ 256
#define L_SZ 64
#define NCH  64
#define BT   (B_SZ * T_SZ)

#define R_SCALE   0.00390625f
#define R_UNSCALE 256.0f

typedef unsigned long long ull;

// ---------------- scratch ---------------------------------------------------
__device__ float g_QKV[3 * BT * C_SZ];       // only V slab (z=2) written fp32
__device__ __half g_xh [BT * V_SZ];          // x hi
__device__ __half g_bTh[C_SZ * V_SZ];        // basis^T hi
__device__ __half g_xbh[BT * C_SZ];          // xb hi
__device__ __half g_xbl[BT * C_SZ];          // xb lo (2-term A for QKV)
__device__ __half g_ch [3 * C_SZ * C_SZ];    // coeffs hi
__device__ __half g_Woh[V_SZ * C_SZ];        // Wo hi (written by sgemm epilogue)
__device__ __half g_QKh[2 * BT * C_SZ];
__device__ __half g_QKl[2 * BT * C_SZ];
__device__ __half g_Vdth[BT * C_SZ];         // decayed V^T [B][C][T] hi
__device__ __half g_Vdtl[BT * C_SZ];
__device__ __half g_Kth[BT * C_SZ];          // K^T [B][C][T] hi
__device__ __half g_Sth[B_SZ * NCH * C_SZ * C_SZ];  // A^T (chunk out), then states in place
__device__ __half g_Rh [BT * C_SZ];          // R hi

__device__ __forceinline__ float get_decay(const float* dl) {
    return 1.0f / (1.0f + expf(-dl[0]));
}

// ---- packed fp32x2 (Wo build only) ----------------------------------------
__device__ __forceinline__ ull pack2(float x) {
    ull r; asm("mov.b64 %0, {%1, %1};" : "=l"(r) : "f"(x)); return r;
}
__device__ __forceinline__ void ffma2(ull& c, ull a, ull b) {
    asm("fma.rn.f32x2 %0, %1, %2, %0;" : "+l"(c) : "l"(a), "l"(b));
}
__device__ __forceinline__ uint32_t cvta_shared(const void* p) {
    uint32_t a;
    asm("{ .reg .u64 t; cvta.to.shared.u64 t, %1; cvt.u32.u64 %0, t; }"
        : "=r"(a) : "l"(p));
    return a;
}

// ---- mma.sync / ldmatrix / cp.async ---------------------------------------
__device__ __forceinline__ void ldsm_x4(uint32_t a, uint32_t* r) {
    asm volatile("ldmatrix.sync.aligned.m8n8.x4.shared.b16 {%0,%1,%2,%3}, [%4];"
                 : "=r"(r[0]), "=r"(r[1]), "=r"(r[2]), "=r"(r[3]) : "r"(a));
}
__device__ __forceinline__ void mma_f16(float* d, const uint32_t* a, const uint32_t* b) {
    asm volatile("mma.sync.aligned.m16n8k16.row.col.f32.f16.f16.f32 "
                 "{%0,%1,%2,%3}, {%4,%5,%6,%7}, {%8,%9}, {%0,%1,%2,%3};"
                 : "+f"(d[0]), "+f"(d[1]), "+f"(d[2]), "+f"(d[3])
                 : "r"(a[0]), "r"(a[1]), "r"(a[2]), "r"(a[3]),
                   "r"(b[0]), "r"(b[1]));
}
__device__ __forceinline__ void cp16(uint32_t dst, const void* src) {
    asm volatile("cp.async.cg.shared.global [%0], [%1], 16;" :: "r"(dst), "l"(src));
}
#define CP_COMMIT() asm volatile("cp.async.commit_group;" ::: "memory")
#define CP_WAIT1()  asm volatile("cp.async.wait_group 1;" ::: "memory")
#define CP_WAIT0()  asm volatile("cp.async.wait_group 0;" ::: "memory")

__device__ __forceinline__ void split_store2(__half* H, __half* L, float v0, float v1) {
    __half h0 = __float2half_rn(v0), h1 = __float2half_rn(v1);
    *(__half2*)H = __half2(h0, h1);
    *(__half2*)L = __half2(__float2half_rn(v0 - __half2float(h0)),
                           __float2half_rn(v1 - __half2float(h1)));
}

// smem geometry for mma_gemm
#define BK 32
#define ROWB 80
#define ARR_B (128 * ROWB)

// ===========================================================================
// fp16 tensor-core GEMM, ATERMS A-side passes (1 or 2): C = A @ Bh^T.
// Epilogue: z < nhz -> fp16 hi/lo split; else fp32.  (R14 fast config, verbatim)
// ===========================================================================
template <int ATERMS>
__global__ void __launch_bounds__(256) mma_gemm(
    const __half* __restrict__ Ahb, const __half* __restrict__ Alb,
    const __half* __restrict__ Bhb,
    float* __restrict__ Cbase, __half* __restrict__ Hout, __half* __restrict__ Lout,
    int nhz, size_t sH, int K, size_t sB, size_t sC, int ldC,
    const float* __restrict__ scale_ptr, float alpha_mul)
{
    extern __shared__ __align__(16) char dynsm[];
    const uint32_t sdyn = cvta_shared(dynsm);
    const uint32_t STAGE_B = (ATERMS + 1) * ARR_B;
    const uint32_t BOFF = ATERMS * ARR_B;

    const int tid = threadIdx.x, lane = tid & 31, wid = tid >> 5;
    const int m0 = blockIdx.y * 128, n0 = blockIdx.x * 128;
    const int z = blockIdx.z;
    const __half* gAh = Ahb + (size_t)m0 * K;
    const __half* gAl = Alb + (size_t)m0 * K;
    const __half* gBh = Bhb + (size_t)z * sB + (size_t)n0 * K;

    const int warp_m = wid >> 1, warp_n = wid & 1;
    const int r8 = lane & 7, midx = lane >> 3;
    const int NC = K / BK;
    const int lr0 = tid >> 2, c4 = tid & 3;

    float acc[2][8][4];
#pragma unroll
    for (int mt = 0; mt < 2; mt++)
#pragma unroll
        for (int nt = 0; nt < 8; nt++)
#pragma unroll
            for (int r = 0; r < 4; r++) acc[mt][nt][r] = 0.0f;

    auto issue = [&](int s, int kc) {
        const int k0 = kc * BK;
        const uint32_t st = sdyn + s * STAGE_B;
#pragma unroll
        for (int h = 0; h < 2; h++) {
            const int r = lr0 + h * 64;
            const uint32_t d = st + r * ROWB + c4 * 16;
            const size_t g = (size_t)r * K + k0 + c4 * 8;
            cp16(d, gAh + g);
            if (ATERMS == 2) cp16(d + ARR_B, gAl + g);
            cp16(d + BOFF, gBh + g);
        }
        CP_COMMIT();
    };

    issue(0, 0);
    issue(1, 1);

    for (int i = 0; i < NC; i++) {
        if (i < NC - 1) CP_WAIT1(); else CP_WAIT0();
        __syncthreads();
        if (i + 2 < NC) issue((i + 2) % 3, i + 2);

        const uint32_t stg = sdyn + (i % 3) * STAGE_B;
#pragma unroll
        for (int kh = 0; kh < 2; kh++) {
            uint32_t ah[2][4], al[2][4], bh4[4][4];
#pragma unroll
            for (int mt = 0; mt < 2; mt++) {
                const uint32_t ad = stg +
                    (warp_m * 32 + mt * 16 + (midx & 1) * 8 + r8) * ROWB +
                    (midx >> 1) * 16 + kh * 32;
                ldsm_x4(ad, ah[mt]);
                if (ATERMS == 2) ldsm_x4(ad + ARR_B, al[mt]);
            }
#pragma unroll
            for (int ng = 0; ng < 4; ng++) {
                const uint32_t bd = stg + BOFF +
                    (warp_n * 64 + ng * 16 + (midx >> 1) * 8 + r8) * ROWB +
                    (midx & 1) * 16 + kh * 32;
                ldsm_x4(bd, bh4[ng]);
            }
#pragma unroll
            for (int mt = 0; mt < 2; mt++)
#pragma unroll
                for (int nt = 0; nt < 8; nt++) {
                    const uint32_t* bp = &bh4[nt >> 1][(nt & 1) * 2];
                    mma_f16(acc[mt][nt], ah[mt], bp);
                    if (ATERMS == 2) mma_f16(acc[mt][nt], al[mt], bp);
                }
        }
    }

    const float alpha = (scale_ptr ? scale_ptr[0] : 1.0f) * alpha_mul;
    const int crow = lane >> 2, ccol = (lane & 3) * 2;
    if (z < nhz) {
        __half* H = Hout + (size_t)z * sH;
        __half* L = Lout + (size_t)z * sH;
#pragma unroll
        for (int mt = 0; mt < 2; mt++)
#pragma unroll
            for (int nt = 0; nt < 8; nt++) {
                const int row = m0 + warp_m * 32 + mt * 16 + crow;
                const int col = n0 + warp_n * 64 + nt * 8 + ccol;
                const size_t o = (size_t)row * ldC + col;
                split_store2(H + o, L + o,
                             acc[mt][nt][0] * alpha, acc[mt][nt][1] * alpha);
                const size_t o2 = o + 8 * (size_t)ldC;
                split_store2(H + o2, L + o2,
                             acc[mt][nt][2] * alpha, acc[mt][nt][3] * alpha);
            }
    } else {
        float* C = Cbase + (size_t)z * sC;
#pragma unroll
        for (int mt = 0; mt < 2; mt++)
#pragma unroll
            for (int nt = 0; nt < 8; nt++) {
                const int row = m0 + warp_m * 32 + mt * 16 + crow;
                const int col = n0 + warp_n * 64 + nt * 8 + ccol;
                float* p = C + (size_t)row * ldC + col;
                *(float2*)p = make_float2(acc[mt][nt][0] * alpha, acc[mt][nt][1] * alpha);
                *(float2*)(p + 8 * (size_t)ldC) =
                    make_float2(acc[mt][nt][2] * alpha, acc[mt][nt][3] * alpha);
            }
    }
}

// ===========================================================================
// chunk_mma: A^T[c2][c1] = sum_r d^r V[r,c2] K[r,c1] per chunk.
// NOW writes fp16 hi directly into g_Sth (scan runs in place on it).
// ===========================================================================
#define CK_STR 144
#define CK_AH 0
#define CK_AL 18432
#define CK_B  36864
#define CK_SMEM 55296

__global__ void __launch_bounds__(256) chunk_mma()
{
    extern __shared__ __align__(16) char csm[];
    const uint32_t s0 = cvta_shared(csm);
    const int z = blockIdx.z, b = z >> 6, c = z & 63;
    const int m0 = blockIdx.y * 128, n0 = blockIdx.x * 128;
    const int tid = threadIdx.x, lane = tid & 31, wid = tid >> 5;
    const int r8 = lane & 7, midx = lane >> 3;

    const size_t tb = (size_t)b * C_SZ * T_SZ + (size_t)c * 64;
    const __half* gAh = g_Vdth + tb + (size_t)m0 * T_SZ;
    const __half* gAl = g_Vdtl + tb + (size_t)m0 * T_SZ;
    const __half* gB  = g_Kth  + tb + (size_t)n0 * T_SZ;

    {
        const int row = tid >> 1, c2_ = tid & 1;
#pragma unroll
        for (int it = 0; it < 4; it++) {
            const int cc = c2_ + it * 2;
            const size_t g = (size_t)row * T_SZ + cc * 8;
            cp16(s0 + CK_AH + row * CK_STR + cc * 16, gAh + g);
            cp16(s0 + CK_AL + row * CK_STR + cc * 16, gAl + g);
            cp16(s0 + CK_B  + row * CK_STR + cc * 16, gB + g);
        }
        CP_COMMIT();
    }
    CP_WAIT0();
    __syncthreads();

    const int wm = wid >> 1, wn = wid & 1;
    float acc[2][8][4];
#pragma unroll
    for (int mt = 0; mt < 2; mt++)
#pragma unroll
        for (int nt = 0; nt < 8; nt++)
#pragma unroll
            for (int e = 0; e < 4; e++) acc[mt][nt][e] = 0.0f;

#pragma unroll
    for (int ks = 0; ks < 4; ks++) {
        uint32_t ah[2][4], al[2][4], bt[4][4];
#pragma unroll
        for (int mt = 0; mt < 2; mt++) {
            const uint32_t ad = s0 + CK_AH +
                (wm * 32 + mt * 16 + (midx & 1) * 8 + r8) * CK_STR +
                (ks * 16 + (midx >> 1) * 8) * 2;
            ldsm_x4(ad, ah[mt]);
            ldsm_x4(ad + (CK_AL - CK_AH), al[mt]);
        }
#pragma unroll
        for (int ng = 0; ng < 4; ng++) {
            const uint32_t bd = s0 + CK_B +
                (wn * 64 + ng * 16 + (midx >> 1) * 8 + r8) * CK_STR +
                (ks * 16 + (midx & 1) * 8) * 2;
            ldsm_x4(bd, bt[ng]);
        }
#pragma unroll
        for (int mt = 0; mt < 2; mt++)
#pragma unroll
            for (int nt = 0; nt < 8; nt++) {
                const uint32_t* bp = &bt[nt >> 1][(nt & 1) * 2];
                mma_f16(acc[mt][nt], ah[mt], bp);
                mma_f16(acc[mt][nt], al[mt], bp);
            }
    }

    __half* O = g_Sth + (size_t)z * C_SZ * C_SZ;
    const int crow = lane >> 2, ccol = (lane & 3) * 2;
#pragma unroll
    for (int mt = 0; mt < 2; mt++)
#pragma unroll
        for (int nt = 0; nt < 8; nt++) {
            const int row = m0 + wm * 32 + mt * 16 + crow;
            const int col = n0 + wn * 64 + nt * 8 + ccol;
            __half* p = O + (size_t)row * C_SZ + col;
            *(__half2*)p = __half2(__float2half_rn(acc[mt][nt][0]),
                                   __float2half_rn(acc[mt][nt][1]));
            *(__half2*)(p + 8 * C_SZ) = __half2(__float2half_rn(acc[mt][nt][2]),
                                                __float2half_rn(acc[mt][nt][3]));
        }
}

// ===========================================================================
// attn (unchanged from R14 fast config)
// ===========================================================================
#define AQ_STR 528
#define AP_STR 144
#define AB_STR 80
#define A_SQH  0
#define A_SQL  33792
#define A_SPH  67584
#define A_SPL  76800
#define A_BUF  86016
#define A_STG  40960
#define A_SMEM 208896

__global__ void __launch_bounds__(256) attn_mma(const float* __restrict__ dlp)
{
    extern __shared__ __align__(16) char asmm[];
    const uint32_t s0 = cvta_shared(asmm);
    const int c = blockIdx.x, b = blockIdx.y;
    const int tid = threadIdx.x, lane = tid & 31, wid = tid >> 5;
    const float lg2d = log2f(get_decay(dlp));

    const size_t nat = ((size_t)b * T_SZ + (size_t)c * L_SZ) * C_SZ;
    const __half* gQh = g_QKh + nat;
    const __half* gQl = g_QKl + nat;
    const __half* gKh = g_QKh + (size_t)BT * C_SZ + nat;
    const __half* gKl = g_QKl + (size_t)BT * C_SZ + nat;
    const size_t vt = (size_t)b * C_SZ * T_SZ + (size_t)c * L_SZ;
    const size_t st = ((size_t)(b * NCH + c)) * C_SZ * C_SZ;

    const int r8 = lane & 7, midx = lane >> 3;

    {
        const int row = tid >> 2, q4 = tid & 3;
#pragma unroll
        for (int it = 0; it < 8; it++) {
            const int c16 = q4 + it * 4;
            cp16(s0 + A_SQH + row * AQ_STR + c16 * 16, gQh + row * C_SZ + c16 * 8);
            cp16(s0 + A_SQL + row * AQ_STR + c16 * 16, gQl + row * C_SZ + c16 * 8);
        }
        CP_COMMIT();
    }

    auto issue = [&](int q) {
        const uint32_t bh = s0 + A_BUF + (q % 3) * A_STG;
        const uint32_t bl = bh + 20480;
        if (q < 8) {
            const int row = tid >> 2, c16 = tid & 3;
            cp16(bh + row * AB_STR + c16 * 16, gKh + row * C_SZ + q * 32 + c16 * 8);
            cp16(bl + row * AB_STR + c16 * 16, gKl + row * C_SZ + q * 32 + c16 * 8);
        } else if (q < 16) {
            const int ct = q - 8;
            const size_t src = st + (size_t)tid * C_SZ + ct * 32;
#pragma unroll
            for (int it = 0; it < 4; it++)
                cp16(bh + tid * AB_STR + it * 16, g_Sth + src + it * 8);
        } else {
            const int ct = q - 16;
            const size_t src = vt + (size_t)tid * T_SZ + ct * 32;
#pragma unroll
            for (int it = 0; it < 4; it++) {
                cp16(bh + tid * AB_STR + it * 16, g_Vdth + src + it * 8);
                cp16(bl + tid * AB_STR + it * 16, g_Vdtl + src + it * 8);
            }
        }
        CP_COMMIT();
    };

    const int pwm = wid & 3, pwn = wid >> 2;
    const int wm = wid & 1, wn = wid >> 1;

    float accp[4][4];
#pragma unroll
    for (int a = 0; a < 4; a++)
#pragma unroll
        for (int e = 0; e < 4; e++) accp[a][e] = 0.0f;
    float acc[2][8][4];
#pragma unroll
    for (int mt = 0; mt < 2; mt++)
#pragma unroll
        for (int nt = 0; nt < 8; nt++)
#pragma unroll
            for (int e = 0; e < 4; e++) acc[mt][nt][e] = 0.0f;

    issue(0);
    issue(1);

    for (int q = 0; q < 18; q++) {
        if (q < 17) CP_WAIT1(); else CP_WAIT0();
        __syncthreads();
        if (q + 2 < 18) issue(q + 2);

        const uint32_t bh = s0 + A_BUF + (q % 3) * A_STG;

        if (q < 8) {
#pragma unroll
            for (int ks = 0; ks < 2; ks++) {
                uint32_t ah[4], al[4];
                const uint32_t ad = s0 + A_SQH +
                    (pwm * 16 + (midx & 1) * 8 + r8) * AQ_STR +
                    (q * 32 + ks * 16 + (midx >> 1) * 8) * 2;
                ldsm_x4(ad, ah);
                ldsm_x4(ad + (A_SQL - A_SQH), al);
#pragma unroll
                for (int ng = 0; ng < 2; ng++) {
                    uint32_t bhf[4], blf[4];
                    const uint32_t bd = bh +
                        (pwn * 32 + ng * 16 + (midx >> 1) * 8 + r8) * AB_STR +
                        (ks * 16 + (midx & 1) * 8) * 2;
                    ldsm_x4(bd, bhf);
                    ldsm_x4(bd + 20480, blf);
#pragma unroll
                    for (int sub = 0; sub < 2; sub++) {
                        float* A = accp[ng * 2 + sub];
                        mma_f16(A, ah, &bhf[sub * 2]);
                        mma_f16(A, al, &bhf[sub * 2]);
                        mma_f16(A, ah, &blf[sub * 2]);
                    }
                }
            }
            if (q == 7) {
                const int prow = pwm * 16 + (lane >> 2);
#pragma unroll
                for (int nt = 0; nt < 4; nt++)
#pragma unroll
                    for (int e = 0; e < 4; e++) {
                        const int i = prow + (e >> 1) * 8;
                        const int j = pwn * 32 + nt * 8 + (lane & 3) * 2 + (e & 1);
                        float v = (j > i) ? accp[nt][e] : 0.0f;
                        __half h = __float2half_rn(v);
                        *(__half*)(asmm + A_SPH + i * AP_STR + j * 2) = h;
                        *(__half*)(asmm + A_SPL + i * AP_STR + j * 2) =
                            __float2half_rn(v - __half2float(h));
                    }
            }
        } else if (q < 16) {
            const int ct = q - 8;
#pragma unroll
            for (int ks = 0; ks < 2; ks++) {
                uint32_t ah[2][4], al[2][4], bh4[4][4];
#pragma unroll
                for (int mt = 0; mt < 2; mt++) {
                    const uint32_t ad = s0 + A_SQH +
                        (wm * 32 + mt * 16 + (midx & 1) * 8 + r8) * AQ_STR +
                        (ct * 32 + ks * 16 + (midx >> 1) * 8) * 2;
                    ldsm_x4(ad, ah[mt]);
                    ldsm_x4(ad + (A_SQL - A_SQH), al[mt]);
                }
#pragma unroll
                for (int ng = 0; ng < 4; ng++) {
                    const uint32_t bd = bh +
                        (wn * 64 + ng * 16 + (midx >> 1) * 8 + r8) * AB_STR +
                        (ks * 16 + (midx & 1) * 8) * 2;
                    ldsm_x4(bd, bh4[ng]);
                }
#pragma unroll
                for (int mt = 0; mt < 2; mt++)
#pragma unroll
                    for (int nt = 0; nt < 8; nt++) {
                        const uint32_t* bp = &bh4[nt >> 1][(nt & 1) * 2];
                        mma_f16(acc[mt][nt], ah[mt], bp);
                        mma_f16(acc[mt][nt], al[mt], bp);
                    }
            }
        } else {
#pragma unroll
            for (int ks = 0; ks < 2; ks++) {
                uint32_t ah[2][4], al[2][4], bh4[4][4], bl4[4][4];
                const int ct = q - 16;
#pragma unroll
                for (int mt = 0; mt < 2; mt++) {
                    const uint32_t ad = s0 + A_SPH +
                        (wm * 32 + mt * 16 + (midx & 1) * 8 + r8) * AP_STR +
                        (ct * 32 + ks * 16 + (midx >> 1) * 8) * 2;
                    ldsm_x4(ad, ah[mt]);
                    ldsm_x4(ad + (A_SPL - A_SPH), al[mt]);
                }
#pragma unroll
                for (int ng = 0; ng < 4; ng++) {
                    const uint32_t bd = bh +
                        (wn * 64 + ng * 16 + (midx >> 1) * 8 + r8) * AB_STR +
                        (ks * 16 + (midx & 1) * 8) * 2;
                    ldsm_x4(bd, bh4[ng]);
                    ldsm_x4(bd + 20480, bl4[ng]);
                }
#pragma unroll
                for (int mt = 0; mt < 2; mt++)
#pragma unroll
                    for (int nt = 0; nt < 8; nt++) {
                        const uint32_t* bp  = &bh4[nt >> 1][(nt & 1) * 2];
                        const uint32_t* blp = &bl4[nt >> 1][(nt & 1) * 2];
                        mma_f16(acc[mt][nt], ah[mt], bp);
                        mma_f16(acc[mt][nt], al[mt], bp);
                        mma_f16(acc[mt][nt], ah[mt], blp);
                    }
            }
        }
    }

    __half* Rh = g_Rh + nat;
#pragma unroll
    for (int mt = 0; mt < 2; mt++) {
        const int i0 = wm * 32 + mt * 16 + (lane >> 2);
        const float s1 = exp2f(-(float)(i0 + 1) * lg2d) * R_SCALE;
        const float s2 = exp2f(-(float)(i0 + 9) * lg2d) * R_SCALE;
#pragma unroll
        for (int nt = 0; nt < 8; nt++) {
            const int col = wn * 64 + nt * 8 + (lane & 3) * 2;
            const size_t o = (size_t)i0 * C_SZ + col;
            *(__half2*)(Rh + o) = __half2(__float2half_rn(acc[mt][nt][0] * s1),
                                          __float2half_rn(acc[mt][nt][1] * s1));
            const size_t o2 = o + 8 * (size_t)C_SZ;
            *(__half2*)(Rh + o2) = __half2(__float2half_rn(acc[mt][nt][2] * s2),
                                           __float2half_rn(acc[mt][nt][3] * s2));
        }
    }
}

// ===========================================================================
// fp32 -> fp16 hi only (x)
// ===========================================================================
__global__ void tohalf_kernel(const float* __restrict__ s,
                              __half* __restrict__ h, int n4)
{
    int i = blockIdx.x * blockDim.x + threadIdx.x;
    if (i >= n4) return;
    float4 v = ((const float4*)s)[i];
    ((__half2*)h)[2 * i]     = __half2(__float2half_rn(v.x), __float2half_rn(v.y));
    ((__half2*)h)[2 * i + 1] = __half2(__float2half_rn(v.z), __float2half_rn(v.w));
}

// ===========================================================================
// 3 coeff tensors -> g_ch (one launch)
// ===========================================================================
__global__ void tohalf3_kernel(const float* __restrict__ a, const float* __restrict__ b,
                               const float* __restrict__ c, __half* __restrict__ h,
                               int n4each)
{
    int i = blockIdx.x * blockDim.x + threadIdx.x;
    if (i >= 3 * n4each) return;
    const int z = i / n4each, j = i - z * n4each;
    const float* s = (z == 0) ? a : (z == 1) ? b : c;
    float4 v = ((const float4*)s)[j];
    __half2* out = (__half2*)h + 2 * (size_t)i;
    out[0] = __half2(__float2half_rn(v.x), __float2half_rn(v.y));
    out[1] = __half2(__float2half_rn(v.z), __float2half_rn(v.w));
}

// ===========================================================================
// basis [1024,256] -> basis^T fp16 hi
// ===========================================================================
__global__ void transpose_half(const float* __restrict__ in,
                               __half* __restrict__ oh)
{
    __shared__ float t[32][33];
    const int v0 = blockIdx.x * 32, c0 = blockIdx.y * 32;
    const int tx = threadIdx.x, ty = threadIdx.y;
#pragma unroll
    for (int j = 0; j < 32; j += 8)
        t[ty + j][tx] = in[(size_t)(v0 + ty + j) * C_SZ + c0 + tx];
    __syncthreads();
#pragma unroll
    for (int j = 0; j < 32; j += 8)
        oh[(size_t)(c0 + ty + j) * V_SZ + v0 + tx] = __float2half_rn(t[tx][ty + j]);
}

// ===========================================================================
// Merged transpose: z<B: V fp32 -> decayed V^T hi/lo; z>=B: K hi -> K^T hi
// grid (T/32, C/32, 2B), block (32, 8)
// ===========================================================================
__global__ void transpose_vk(const float* __restrict__ Vin,
                             const __half* __restrict__ Kin,
                             __half* __restrict__ Vdth, __half* __restrict__ Vdtl,
                             __half* __restrict__ Kth,
                             const float* __restrict__ dlp)
{
    __shared__ float t[32][33];
    const int zz = blockIdx.z;
    const int t0 = blockIdx.x * 32, c0 = blockIdx.y * 32;
    const int tx = threadIdx.x, ty = threadIdx.y;

    if (zz < B_SZ) {
        const int b = zz;
        const float lg2d = log2f(get_decay(dlp));
        const float dr = exp2f((float)((t0 + tx) & 63) * lg2d);
#pragma unroll
        for (int j = 0; j < 32; j += 8)
            t[ty + j][tx] = Vin[((size_t)b * T_SZ + t0 + ty + j) * C_SZ + c0 + tx];
        __syncthreads();
#pragma unroll
        for (int j = 0; j < 32; j += 8) {
            float val = t[tx][ty + j] * dr;
            __half h = __float2half_rn(val);
            const size_t o = (size_t)b * C_SZ * T_SZ + (size_t)(c0 + ty + j) * T_SZ + t0 + tx;
            Vdth[o] = h;
            Vdtl[o] = __float2half_rn(val - __half2float(h));
        }
    } else {
        const int b = zz - B_SZ;
#pragma unroll
        for (int j = 0; j < 32; j += 8)
            t[ty + j][tx] = __half2float(
                Kin[((size_t)b * T_SZ + t0 + ty + j) * C_SZ + c0 + tx]);
        __syncthreads();
#pragma unroll
        for (int j = 0; j < 32; j += 8)
            Kth[(size_t)b * C_SZ * T_SZ + (size_t)(c0 + ty + j) * T_SZ + t0 + tx] =
                __float2half_rn(t[tx][ty + j]);   // exact round-trip
    }
}

// ===========================================================================
// SGEMM nt (f32x2) — Wo build, writes fp16 hi directly
// ===========================================================================
__global__ void __launch_bounds__(256) sgemm_nt_h(
    const float* __restrict__ A, const float* __restrict__ B,
    __half* __restrict__ C, int M, int N, int K)
{
    __shared__ __align__(16) float As[8][128];
    __shared__ __align__(16) float Bs[8][128];
    const int tid = threadIdx.x;
    const int m0 = blockIdx.y * 128, n0 = blockIdx.x * 128;
    const int tr = tid >> 4, tc = tid & 15;
    const int ar = tid >> 1, ac = (tid & 1) * 4;
    ull acc[8][4] = {};
    const float* Aptr = A + (size_t)(m0 + ar) * K + ac;
    const float* Bptr = B + (size_t)(n0 + ar) * K + ac;
    for (int k0 = 0; k0 < K; k0 += 8) {
        float4 av = *(const float4*)(Aptr + k0);
        As[ac + 0][ar] = av.x; As[ac + 1][ar] = av.y;
        As[ac + 2][ar] = av.z; As[ac + 3][ar] = av.w;
        float4 bv = *(const float4*)(Bptr + k0);
        Bs[ac + 0][ar] = bv.x; Bs[ac + 1][ar] = bv.y;
        Bs[ac + 2][ar] = bv.z; Bs[ac + 3][ar] = bv.w;
        __syncthreads();
#pragma unroll
        for (int kk = 0; kk < 8; kk++) {
            const ull* bp = (const ull*)&Bs[kk][tc * 8];
            ull b0 = bp[0], b1 = bp[1], b2 = bp[2], b3 = bp[3];
            const float* ap = &As[kk][tr * 8];
#pragma unroll
            for (int i = 0; i < 8; i++) {
                ull a2 = pack2(ap[i]);
                ffma2(acc[i][0], a2, b0); ffma2(acc[i][1], a2, b1);
                ffma2(acc[i][2], a2, b2); ffma2(acc[i][3], a2, b3);
            }
        }
        __syncthreads();
    }
#pragma unroll
    for (int i = 0; i < 8; i++) {
        __half* Cp = C + (size_t)(m0 + tr * 8 + i) * N + n0 + tc * 8;
#pragma unroll
        for (int j = 0; j < 4; j++) {
            float2 p = *(float2*)&acc[i][j];
            *(__half2*)(Cp + 2 * j) = __half2(__float2half_rn(p.x), __float2half_rn(p.y));
        }
    }
}

// ===========================================================================
// scan (in place on g_Sth): a = buf[pos]; sc = dL*run; buf[pos] = sc; run = sc + a
// ===========================================================================
__global__ void scan_kernel(const float* __restrict__ dlp)
{
    const int e = blockIdx.x * blockDim.x + threadIdx.x;
    const int b = blockIdx.y;
    const float decay = get_decay(dlp);
    const float dL = exp2f((float)L_SZ * log2f(decay));
    float run = 0.0f;
    const size_t base = (size_t)b * NCH * (C_SZ * C_SZ) + e;
    for (int c = NCH - 1; c >= 0; c--) {
        const size_t pos = base + (size_t)c * (C_SZ * C_SZ);
        const float a = __half2float(g_Sth[pos]);
        const float sc_ = dL * run;
        g_Sth[pos] = __float2half_rn(sc_);
        run = sc_ + a;
    }
}

// ===========================================================================
extern "C" void kernel_launch(void* const* d_in, const int* in_sizes, int n_in,
                              void* d_out, int out_size)
{
    const float* x     = (const float*)d_in[0];
    const float* basis = (const float*)d_in[1];
    const float* qc    = (const float*)d_in[2];
    const float* kc    = (const float*)d_in[3];
    const float* vc    = (const float*)d_in[4];
    const float* oc    = (const float*)d_in[5];
    const float* dl    = (const float*)d_in[6];
    const float* os    = (const float*)d_in[7];
    float* out = (float*)d_out;

    float *pQKV;
    __half *pxh, *pbTh, *pxbh, *pxbl, *pch, *pWoh;
    __half *pQKh, *pQKl, *pVdth, *pVdtl, *pKth, *pRh;
    cudaGetSymbolAddress((void**)&pQKV,  g_QKV);
    cudaGetSymbolAddress((void**)&pxh,   g_xh);
    cudaGetSymbolAddress((void**)&pbTh,  g_bTh);
    cudaGetSymbolAddress((void**)&pxbh,  g_xbh);
    cudaGetSymbolAddress((void**)&pxbl,  g_xbl);
    cudaGetSymbolAddress((void**)&pch,   g_ch);
    cudaGetSymbolAddress((void**)&pWoh,  g_Woh);
    cudaGetSymbolAddress((void**)&pQKh,  g_QKh);
    cudaGetSymbolAddress((void**)&pQKl,  g_QKl);
    cudaGetSymbolAddress((void**)&pVdth, g_Vdth);
    cudaGetSymbolAddress((void**)&pVdtl, g_Vdtl);
    cudaGetSymbolAddress((void**)&pKth,  g_Kth);
    cudaGetSymbolAddress((void**)&pRh,   g_Rh);

    const int SMEM_A1 = 3 * 2 * ARR_B;   // 61440
    const int SMEM_A2 = 3 * 3 * ARR_B;   // 92160
    cudaFuncSetAttribute(mma_gemm<1>, cudaFuncAttributeMaxDynamicSharedMemorySize, SMEM_A1);
    cudaFuncSetAttribute(mma_gemm<2>, cudaFuncAttributeMaxDynamicSharedMemorySize, SMEM_A2);
    cudaFuncSetAttribute(chunk_mma, cudaFuncAttributeMaxDynamicSharedMemorySize, CK_SMEM);
    cudaFuncSetAttribute(attn_mma, cudaFuncAttributeMaxDynamicSharedMemorySize, A_SMEM);

    // 1. prep (4 launches): basis^T hi, x hi, coeffs hi (fused), Wo build->hi
    transpose_half<<<dim3(32, 8), dim3(32, 8)>>>(basis, pbTh);
    tohalf_kernel<<<(BT * V_SZ / 4 + 255) / 256, 256>>>(x, pxh, BT * V_SZ / 4);
    tohalf3_kernel<<<(3 * C_SZ * C_SZ / 4 + 255) / 256, 256>>>(
        qc, kc, vc, pch, C_SZ * C_SZ / 4);
    sgemm_nt_h<<<dim3(2, 8), 256>>>(basis, oc, pWoh, 1024, 256, 256);

    // 2. xb = x @ basis (1-term A) -> fp16 hi/lo
    mma_gemm<1><<<dim3(2, 128, 1), 256, SMEM_A1>>>(
        pxh, pxh, pbTh, pQKV /*dummy*/, pxbh, pxbl, 1, 0,
        V_SZ, 0, 0, C_SZ, nullptr, 1.0f);

    // 3. QKV = xb @ coeffs^T (2-term A): z=0,1 -> Q/K fp16 hi/lo; z=2 -> V fp32
    mma_gemm<2><<<dim3(2, 128, 3), 256, SMEM_A2>>>(
        pxbh, pxbl, pch, pQKV, pQKh, pQKl, 2, (size_t)BT * C_SZ,
        C_SZ, (size_t)C_SZ * C_SZ, (size_t)BT * C_SZ, C_SZ, nullptr, 1.0f);

    // 4. merged transposes: decayed V^T hi/lo + K^T hi (one launch)
    transpose_vk<<<dim3(128, 8, 2 * B_SZ), dim3(32, 8)>>>(
        pQKV + 2 * (size_t)BT * C_SZ, pQKh + (size_t)BT * C_SZ,
        pVdth, pVdtl, pKth, dl);

    // 5. chunk A^T -> g_Sth (fp16), scan in place, attn -> Rh
    chunk_mma<<<dim3(2, 2, B_SZ * NCH), 256, CK_SMEM>>>();
    scan_kernel<<<dim3(256, B_SZ), 256>>>(dl);
    attn_mma<<<dim3(NCH, B_SZ), 256, A_SMEM>>>(dl);

    // 6. output projection: out = R @ Wo^T * out_scale (1-term A)
    mma_gemm<1><<<dim3(8, 128, 1), 256, SMEM_A1>>>(
        pRh, pRh, pWoh, out, nullptr, nullptr, 0, 0,
        C_SZ, 0, 0, V_SZ, os, R_UNSCALE);
}